// round 7
// baseline (speedup 1.0000x reference)
#include <cuda_runtime.h>
#include <cstdint>

// Batched GEMM via mma.sync tf32 (raw fp32 bits), round-7 change:
// staging via cp.async.bulk (UBLKCP, engine-offloaded row copies) + mbarrier
// instead of 2048 per-CTA-kt LDGSTS ops, which were the measured issue-path
// roof (tensor% pinned at 46% across otherwise different configs).
//
//   x:    [B=16, M=256, K=512]  (K contiguous)
//   path: [B=16, K=512, N=2048] (N contiguous)
//   out:  [B=16, M=256, N=2048]
//
// CTA tile 128x128, BK=32, 128 threads (4 warps, warp tile 64x64),
// 3-stage pipeline, 2 CTAs/SM. Per stage: A rows = 128 x 128B bulk copies,
// B rows = 32 x 512B bulk copies, spread across warps (<=2 per lane).

constexpr int Mm = 256, Kk = 512, Nn = 2048;
constexpr int BM = 128, BN = 128, BK = 32;
constexpr int THREADS = 128;
constexpr int KT = Kk / BK;  // 16
constexpr int NSTAGE = 3;

constexpr int A_STRIDE = BK + 4;    // 36 floats (144B rows)
constexpr int B_STRIDE = BN + 8;    // 136 floats (544B rows)
constexpr int A_STAGE = BM * A_STRIDE;          // 4608 floats
constexpr int B_STAGE = BK * B_STRIDE;          // 4352 floats
constexpr int STAGE_FLOATS = A_STAGE + B_STAGE; // 8960 floats = 35840 B
constexpr int STAGE_BYTES = STAGE_FLOATS * 4;
constexpr int DATA_OFF = 128;  // bytes; mbarriers live in [0,24)
constexpr int SMEM_BYTES = DATA_OFF + NSTAGE * STAGE_BYTES;  // 107648
constexpr uint32_t TX_PER_WARP = 32 * 128 + 8 * 512;  // 8192 B

__device__ __forceinline__ uint32_t smem_u32(const void* ptr) {
    uint32_t a;
    asm("{ .reg .u64 t; cvta.to.shared.u64 t, %1; cvt.u32.u64 %0, t; }"
        : "=r"(a) : "l"(ptr));
    return a;
}
__device__ __forceinline__ void mbar_init(uint32_t a, uint32_t n) {
    asm volatile("mbarrier.init.shared.b64 [%0], %1;" :: "r"(a), "r"(n) : "memory");
}
__device__ __forceinline__ void mbar_expect_tx(uint32_t a, uint32_t bytes) {
    asm volatile("mbarrier.arrive.expect_tx.shared.b64 _, [%0], %1;"
                 :: "r"(a), "r"(bytes) : "memory");
}
__device__ __forceinline__ void mbar_wait(uint32_t a, uint32_t parity) {
    asm volatile(
        "{\n\t.reg .pred P;\n\t"
        "W_%=:\n\t"
        "mbarrier.try_wait.parity.acquire.cta.shared::cta.b64 P, [%0], %1, 0x989680;\n\t"
        "@!P bra W_%=;\n\t}"
        :: "r"(a), "r"(parity) : "memory");
}
__device__ __forceinline__ void bulk_g2s(uint32_t dst, const void* src,
                                         uint32_t bytes, uint32_t mbar) {
    asm volatile(
        "cp.async.bulk.shared::cta.global.mbarrier::complete_tx::bytes "
        "[%0], [%1], %2, [%3];"
        :: "r"(dst), "l"(src), "r"(bytes), "r"(mbar) : "memory");
}
__device__ __forceinline__ void mma_tf32(float& c0, float& c1, float& c2, float& c3,
                                         uint32_t a0, uint32_t a1, uint32_t a2, uint32_t a3,
                                         uint32_t b0, uint32_t b1) {
    asm volatile(
        "mma.sync.aligned.m16n8k8.row.col.f32.tf32.tf32.f32 "
        "{%0,%1,%2,%3}, {%4,%5,%6,%7}, {%8,%9}, {%0,%1,%2,%3};"
        : "+f"(c0), "+f"(c1), "+f"(c2), "+f"(c3)
        : "r"(a0), "r"(a1), "r"(a2), "r"(a3), "r"(b0), "r"(b1));
}

__global__ __launch_bounds__(THREADS, 2)
void bmm_mma_tf32_blk(const float* __restrict__ A,
                      const float* __restrict__ B,
                      float* __restrict__ C) {
    extern __shared__ float smem[];
    const uint32_t sb = smem_u32(smem);
    float* data = smem + DATA_OFF / 4;

    const int tid = threadIdx.x;
    const int wid = tid >> 5;
    const int lane = tid & 31;
    const int b  = blockIdx.z;
    const int by = blockIdx.y;
    const int n0 = blockIdx.x * BN;

    const float* Ab = A + (size_t)b * Mm * Kk + (size_t)by * BM * Kk;
    const float* Bb = B + (size_t)b * Kk * Nn + n0;
    float*       Cb = C + (size_t)b * Mm * Nn + (size_t)by * BM * Nn + n0;

    if (tid == 0) {
#pragma unroll
        for (int s = 0; s < NSTAGE; s++) mbar_init(sb + 8 * s, 4);
    }
    __syncthreads();

    // ---- bulk-copy mappings: 1 A row per thread, 1 B row for lanes 0-7 ----
    const int a_row = wid * 32 + lane;                   // 0..127
    const float* a_src = Ab + (size_t)a_row * Kk;        // + kt*BK
    const uint32_t a_dst = sb + DATA_OFF + a_row * (A_STRIDE * 4);
    const int b_row = wid * 8 + lane;                    // valid for lane<8
    const float* b_src = Bb + (size_t)b_row * Nn;        // + kt*BK*Nn
    const uint32_t b_dst = sb + DATA_OFF + A_STAGE * 4 + b_row * (B_STRIDE * 4);

    auto issue_stage = [&](int kt, int s) {
        const uint32_t mb = sb + 8 * s;
        const uint32_t soff = s * STAGE_BYTES;
        if (lane == 0) mbar_expect_tx(mb, TX_PER_WARP);
        __syncwarp();
        bulk_g2s(a_dst + soff, a_src + (size_t)kt * BK, BK * 4, mb);
        if (lane < 8)
            bulk_g2s(b_dst + soff, b_src + (size_t)kt * BK * Nn, BN * 4, mb);
    };

    // ---- compute mapping: 4 warps, 2x2 of 64x64 warp tiles ----
    const int warp_m = wid >> 1;
    const int warp_n = wid & 1;
    const int m_base = warp_m * 64;
    const int nb     = warp_n * 64;
    const int g = lane >> 2;
    const int t = lane & 3;

    float acc[4][8][4];
#pragma unroll
    for (int i = 0; i < 4; i++)
#pragma unroll
        for (int j = 0; j < 8; j++)
#pragma unroll
            for (int r = 0; r < 4; r++) acc[i][j][r] = 0.0f;

    uint32_t af[2][4][4];
    uint32_t bf[2][8][2];

    issue_stage(0, 0);
    issue_stage(1, 1);

    int ph0 = 0, ph1 = 0, ph2 = 0;

#pragma unroll 1
    for (int kt = 0; kt < KT; kt++) {
        const int s = kt % NSTAGE;
        int ph = (s == 0) ? ph0 : (s == 1) ? ph1 : ph2;
        mbar_wait(sb + 8 * s, ph);
        if (s == 0) ph0 ^= 1; else if (s == 1) ph1 ^= 1; else ph2 ^= 1;
        __syncthreads();  // all threads past prior compute on stage (kt+2)%3

        if (kt + 2 < KT) issue_stage(kt + 2, (kt + 2) % NSTAGE);

        const float* As = data + s * STAGE_FLOATS;
        const float* Bs = As + A_STAGE;

        auto load_frags = [&](int ks, int bsel) {
            const int k0 = ks * 8;
#pragma unroll
            for (int i = 0; i < 4; i++) {
                const float* ap = As + (m_base + i * 16 + g) * A_STRIDE + k0 + t;
                af[bsel][i][0] = __float_as_uint(ap[0]);
                af[bsel][i][1] = __float_as_uint(ap[8 * A_STRIDE]);
                af[bsel][i][2] = __float_as_uint(ap[4]);
                af[bsel][i][3] = __float_as_uint(ap[8 * A_STRIDE + 4]);
            }
#pragma unroll
            for (int j = 0; j < 8; j++) {
                const float* bp = Bs + (k0 + t) * B_STRIDE + nb + j * 8 + g;
                bf[bsel][j][0] = __float_as_uint(bp[0]);
                bf[bsel][j][1] = __float_as_uint(bp[4 * B_STRIDE]);
            }
        };

        load_frags(0, 0);
#pragma unroll
        for (int ks = 0; ks < 4; ks++) {
            const int cur = ks & 1;
            if (ks < 3) load_frags(ks + 1, cur ^ 1);
#pragma unroll
            for (int i = 0; i < 4; i++)
#pragma unroll
                for (int j = 0; j < 8; j++)
                    mma_tf32(acc[i][j][0], acc[i][j][1], acc[i][j][2], acc[i][j][3],
                             af[cur][i][0], af[cur][i][1], af[cur][i][2], af[cur][i][3],
                             bf[cur][j][0], bf[cur][j][1]);
        }
    }

    // ---- epilogue ----
#pragma unroll
    for (int i = 0; i < 4; i++) {
        const int row0 = m_base + i * 16 + g;
#pragma unroll
        for (int j = 0; j < 8; j++) {
            const int col = nb + j * 8 + 2 * t;
            *(float2*)(Cb + (size_t)row0 * Nn + col) =
                make_float2(acc[i][j][0], acc[i][j][1]);
            *(float2*)(Cb + (size_t)(row0 + 8) * Nn + col) =
                make_float2(acc[i][j][2], acc[i][j][3]);
        }
    }
}

extern "C" void kernel_launch(void* const* d_in, const int* in_sizes, int n_in,
                              void* d_out, int out_size) {
    const float* x    = (const float*)d_in[0];  // [16, 256, 512]
    const float* path = (const float*)d_in[1];  // [16, 512, 2048]
    float* out = (float*)d_out;                 // [16, 256, 2048]

    cudaFuncSetAttribute(bmm_mma_tf32_blk,
                         cudaFuncAttributeMaxDynamicSharedMemorySize, SMEM_BYTES);

    dim3 grid(Nn / BN, Mm / BM, 16);  // (16, 2, 16) = 512 CTAs
    bmm_mma_tf32_blk<<<grid, THREADS, SMEM_BYTES>>>(x, path, out);
}

// round 8
// speedup vs baseline: 1.3364x; 1.3364x over previous
#include <cuda_runtime.h>
#include <cstdint>

// Batched GEMM via mma.sync fp16 m16n8k16 (fp32 accumulate).
// Round-8: same proven cp.async fp32 staging + 3-stage pipeline as round 6;
// fragments are converted fp32->fp16 (cvt.rn.f16x2) after LDS. fp16 HMMA has
// 2x the MAC rate of tf32 (which round-5/6 data shows we had saturated), and
// fp16's 10-bit mantissa == tf32's, so rel_err ~ the cvt.rna tf32 run (2.8e-4).
//
//   x:    [B=16, M=256, K=512]  (K contiguous)
//   path: [B=16, K=512, N=2048] (N contiguous)
//   out:  [B=16, M=256, N=2048]
//
// CTA tile 128x128, BK=32, 128 threads (4 warps, warp tile 64x64), 2 CTAs/SM.

constexpr int Mm = 256, Kk = 512, Nn = 2048;
constexpr int BM = 128, BN = 128, BK = 32;
constexpr int THREADS = 128;
constexpr int KT = Kk / BK;  // 16
constexpr int NSTAGE = 3;

constexpr int A_STRIDE = BK + 4;    // 36 floats
constexpr int B_STRIDE = BN + 4;    // 132 floats (528B rows, 16B-aligned;
                                    // makes (2t)-row fragment reads conflict-free)
constexpr int A_STAGE = BM * A_STRIDE;          // 4608 floats
constexpr int B_STAGE = BK * B_STRIDE;          // 4224 floats
constexpr int STAGE_FLOATS = A_STAGE + B_STAGE; // 8832 floats = 35328 B
constexpr int SMEM_BYTES = NSTAGE * STAGE_FLOATS * 4;  // 105984 B

__device__ __forceinline__ uint32_t smem_u32(const void* ptr) {
    uint32_t a;
    asm("{ .reg .u64 t; cvta.to.shared.u64 t, %1; cvt.u32.u64 %0, t; }"
        : "=r"(a) : "l"(ptr));
    return a;
}

__device__ __forceinline__ void cp_async16(uint32_t dst, const void* src) {
    asm volatile("cp.async.cg.shared.global [%0], [%1], 16;"
                 :: "r"(dst), "l"(src) : "memory");
}
__device__ __forceinline__ void cp_commit() {
    asm volatile("cp.async.commit_group;" ::: "memory");
}
template <int N>
__device__ __forceinline__ void cp_wait() {
    asm volatile("cp.async.wait_group %0;" :: "n"(N) : "memory");
}

// pack two fp32 into f16x2: lo half = first arg, hi half = second arg
__device__ __forceinline__ uint32_t h2pack(float lo, float hi) {
    uint32_t r;
    asm("cvt.rn.f16x2.f32 %0, %1, %2;" : "=r"(r) : "f"(hi), "f"(lo));
    return r;
}

__device__ __forceinline__ void mma_f16(float& c0, float& c1, float& c2, float& c3,
                                        uint32_t a0, uint32_t a1, uint32_t a2, uint32_t a3,
                                        uint32_t b0, uint32_t b1) {
    asm volatile(
        "mma.sync.aligned.m16n8k16.row.col.f32.f16.f16.f32 "
        "{%0,%1,%2,%3}, {%4,%5,%6,%7}, {%8,%9}, {%0,%1,%2,%3};"
        : "+f"(c0), "+f"(c1), "+f"(c2), "+f"(c3)
        : "r"(a0), "r"(a1), "r"(a2), "r"(a3), "r"(b0), "r"(b1));
}

__global__ __launch_bounds__(THREADS, 2)
void bmm_mma_f16(const float* __restrict__ A,
                 const float* __restrict__ B,
                 float* __restrict__ C) {
    extern __shared__ float smem[];
    const uint32_t smem_base = smem_u32(smem);

    const int tid = threadIdx.x;
    const int wid = tid >> 5;
    const int lane = tid & 31;
    const int b  = blockIdx.z;
    const int by = blockIdx.y;
    const int n0 = blockIdx.x * BN;

    const float* Ab = A + (size_t)b * Mm * Kk + (size_t)by * BM * Kk;
    const float* Bb = B + (size_t)b * Kk * Nn + n0;
    float*       Cb = C + (size_t)b * Mm * Nn + (size_t)by * BM * Nn + n0;

    // ---- cp.async mappings (8 x 16B chunks each for A and B per thread) ----
    const float* aSrc[8];
    const float* bSrc[8];
    uint32_t aDst[8], bDst[8];
#pragma unroll
    for (int j = 0; j < 8; j++) {
        int i = j * 128 + tid;
        int row = i >> 3, kq = (i & 7) * 4;
        aSrc[j] = Ab + (size_t)row * Kk + kq;
        aDst[j] = smem_base + (row * A_STRIDE + kq) * 4;
        int krow = i >> 5, n = (i & 31) * 4;
        bSrc[j] = Bb + (size_t)krow * Nn + n;
        bDst[j] = smem_base + (A_STAGE + krow * B_STRIDE + n) * 4;
    }

    auto issue_stage = [&](int kt, int s) {
        const uint32_t soff = s * (STAGE_FLOATS * 4);
        const size_t ga = (size_t)kt * BK;
        const size_t gb = (size_t)kt * BK * Nn;
#pragma unroll
        for (int j = 0; j < 8; j++) cp_async16(aDst[j] + soff, aSrc[j] + ga);
#pragma unroll
        for (int j = 0; j < 8; j++) cp_async16(bDst[j] + soff, bSrc[j] + gb);
        cp_commit();
    };

    // ---- compute mapping: 4 warps, 2x2 of 64x64 warp tiles ----
    const int warp_m = wid >> 1;
    const int warp_n = wid & 1;
    const int m_base = warp_m * 64;
    const int nb     = warp_n * 64;
    const int g = lane >> 2;            // 0..7
    const int t = lane & 3;             // 0..3

    float acc[4][8][4];
#pragma unroll
    for (int i = 0; i < 4; i++)
#pragma unroll
        for (int j = 0; j < 8; j++)
#pragma unroll
            for (int r = 0; r < 4; r++) acc[i][j][r] = 0.0f;

    uint32_t af[2][4][4];
    uint32_t bf[2][8][2];

    issue_stage(0, 0);
    issue_stage(1, 1);

#pragma unroll 1
    for (int kt = 0; kt < KT; kt++) {
        if (kt == KT - 1) cp_wait<0>(); else cp_wait<1>();
        __syncthreads();

        if (kt + 2 < KT) issue_stage(kt + 2, (kt + 2) % NSTAGE);

        const float* As = smem + (kt % NSTAGE) * STAGE_FLOATS;
        const float* Bs = As + A_STAGE;

        // fragment load for one k16 step (fp32 LDS -> f16x2 pack)
        auto load_frags = [&](int ks, int bsel) {
            const int k0 = ks * 16;
#pragma unroll
            for (int i = 0; i < 4; i++) {
                const float* ap = As + (m_base + i * 16 + g) * A_STRIDE + k0 + 2 * t;
                float2 v0 = *(const float2*)(ap);
                float2 v1 = *(const float2*)(ap + 8 * A_STRIDE);
                float2 v2 = *(const float2*)(ap + 8);
                float2 v3 = *(const float2*)(ap + 8 * A_STRIDE + 8);
                af[bsel][i][0] = h2pack(v0.x, v0.y);
                af[bsel][i][1] = h2pack(v1.x, v1.y);
                af[bsel][i][2] = h2pack(v2.x, v2.y);
                af[bsel][i][3] = h2pack(v3.x, v3.y);
            }
#pragma unroll
            for (int j = 0; j < 8; j++) {
                const float* bp = Bs + (k0 + 2 * t) * B_STRIDE + nb + j * 8 + g;
                bf[bsel][j][0] = h2pack(bp[0], bp[B_STRIDE]);
                bf[bsel][j][1] = h2pack(bp[8 * B_STRIDE], bp[9 * B_STRIDE]);
            }
        };

        load_frags(0, 0);
#pragma unroll
        for (int ks = 0; ks < 2; ks++) {   // 2 x k16 per BK=32
            const int cur = ks & 1;
            if (ks < 1) load_frags(ks + 1, cur ^ 1);
#pragma unroll
            for (int i = 0; i < 4; i++)
#pragma unroll
                for (int j = 0; j < 8; j++)
                    mma_f16(acc[i][j][0], acc[i][j][1], acc[i][j][2], acc[i][j][3],
                            af[cur][i][0], af[cur][i][1], af[cur][i][2], af[cur][i][3],
                            bf[cur][j][0], bf[cur][j][1]);
        }
    }

    // ---- epilogue (same C layout as m16n8k8) ----
#pragma unroll
    for (int i = 0; i < 4; i++) {
        const int row0 = m_base + i * 16 + g;
#pragma unroll
        for (int j = 0; j < 8; j++) {
            const int col = nb + j * 8 + 2 * t;
            *(float2*)(Cb + (size_t)row0 * Nn + col) =
                make_float2(acc[i][j][0], acc[i][j][1]);
            *(float2*)(Cb + (size_t)(row0 + 8) * Nn + col) =
                make_float2(acc[i][j][2], acc[i][j][3]);
        }
    }
}

extern "C" void kernel_launch(void* const* d_in, const int* in_sizes, int n_in,
                              void* d_out, int out_size) {
    const float* x    = (const float*)d_in[0];  // [16, 256, 512]
    const float* path = (const float*)d_in[1];  // [16, 512, 2048]
    float* out = (float*)d_out;                 // [16, 256, 2048]

    cudaFuncSetAttribute(bmm_mma_f16,
                         cudaFuncAttributeMaxDynamicSharedMemorySize, SMEM_BYTES);

    dim3 grid(Nn / BN, Mm / BM, 16);  // (16, 2, 16) = 512 CTAs
    bmm_mma_f16<<<grid, THREADS, SMEM_BYTES>>>(x, path, out);
}

// round 9
// speedup vs baseline: 1.5815x; 1.1834x over previous
#include <cuda_runtime.h>
#include <cstdint>

// Batched GEMM via mma.sync fp16 m16n8k16 + ldmatrix operand feeding.
// Round-9: smem holds fp16 tiles (converted once during staging via
// LDG.128 -> cvt.rn.f16x2 -> STS.64); inner loop is 16 ldmatrix.x4 + 64 HMMA
// per warp-kt (was 48 LDS + 48 cvt + 64 HMMA). Conflict-free padded strides.
//
//   x:    [B=16, M=256, K=512]  (K contiguous)
//   path: [B=16, K=512, N=2048] (N contiguous)
//   out:  [B=16, M=256, N=2048]
//
// CTA tile 128x128, BK=32, 128 threads (4 warps, warp tile 64x64),
// 2-stage double buffer, 2 CTAs/SM. Static smem (37.9 KB).

constexpr int Mm = 256, Kk = 512, Nn = 2048;
constexpr int BM = 128, BN = 128, BK = 32;
constexpr int THREADS = 128;
constexpr int KT = Kk / BK;  // 16

constexpr int A_STRIDE_H = 40;   // fp16 units (80B rows: 8-row ldmatrix phase hits all banks)
constexpr int B_STRIDE_H = 136;  // fp16 units (272B rows: bank-start 4r, conflict-free)
constexpr int A_STAGE_B = BM * A_STRIDE_H * 2;   // 10240 B
constexpr int B_STAGE_B = BK * B_STRIDE_H * 2;   // 8704 B
constexpr int STAGE_B   = A_STAGE_B + B_STAGE_B; // 18944 B

__device__ __forceinline__ uint32_t smem_u32(const void* ptr) {
    uint32_t a;
    asm("{ .reg .u64 t; cvta.to.shared.u64 t, %1; cvt.u32.u64 %0, t; }"
        : "=r"(a) : "l"(ptr));
    return a;
}

// pack two fp32 into f16x2: lo half = first arg, hi half = second arg
__device__ __forceinline__ uint32_t h2pack(float lo, float hi) {
    uint32_t r;
    asm("cvt.rn.f16x2.f32 %0, %1, %2;" : "=r"(r) : "f"(hi), "f"(lo));
    return r;
}

__device__ __forceinline__ void ldmatrix_x4(uint32_t& r0, uint32_t& r1,
                                            uint32_t& r2, uint32_t& r3, uint32_t addr) {
    asm volatile("ldmatrix.sync.aligned.m8n8.x4.shared.b16 {%0,%1,%2,%3}, [%4];"
                 : "=r"(r0), "=r"(r1), "=r"(r2), "=r"(r3) : "r"(addr));
}
__device__ __forceinline__ void ldmatrix_x4_trans(uint32_t& r0, uint32_t& r1,
                                                  uint32_t& r2, uint32_t& r3, uint32_t addr) {
    asm volatile("ldmatrix.sync.aligned.m8n8.x4.trans.shared.b16 {%0,%1,%2,%3}, [%4];"
                 : "=r"(r0), "=r"(r1), "=r"(r2), "=r"(r3) : "r"(addr));
}

__device__ __forceinline__ void mma_f16(float& c0, float& c1, float& c2, float& c3,
                                        uint32_t a0, uint32_t a1, uint32_t a2, uint32_t a3,
                                        uint32_t b0, uint32_t b1) {
    asm volatile(
        "mma.sync.aligned.m16n8k16.row.col.f32.f16.f16.f32 "
        "{%0,%1,%2,%3}, {%4,%5,%6,%7}, {%8,%9}, {%0,%1,%2,%3};"
        : "+f"(c0), "+f"(c1), "+f"(c2), "+f"(c3)
        : "r"(a0), "r"(a1), "r"(a2), "r"(a3), "r"(b0), "r"(b1));
}

__global__ __launch_bounds__(THREADS, 2)
void bmm_mma_f16_ldm(const float* __restrict__ A,
                     const float* __restrict__ B,
                     float* __restrict__ C) {
    __shared__ __align__(16) char smem_raw[2 * STAGE_B];
    const uint32_t sb = smem_u32(smem_raw);

    const int tid = threadIdx.x;
    const int wid = tid >> 5;
    const int lane = tid & 31;
    const int b  = blockIdx.z;
    const int by = blockIdx.y;
    const int n0 = blockIdx.x * BN;

    const float* Ab = A + (size_t)b * Mm * Kk + (size_t)by * BM * Kk;
    const float* Bb = B + (size_t)b * Kk * Nn + n0;
    float*       Cb = C + (size_t)b * Mm * Nn + (size_t)by * BM * Nn + n0;

    // ---- staging mappings: 8 float4 chunks each of A and B per thread ----
    // A tile: 128 rows x 32 floats -> chunk i: row = i>>3, kq = (i&7)*4
    // B tile: 32 rows x 128 floats -> chunk i: krow = i>>5, n = (i&31)*4
    const float* aSrc[8];
    const float* bSrc[8];
    uint32_t aSt[8], bSt[8];
#pragma unroll
    for (int j = 0; j < 8; j++) {
        int i = j * 128 + tid;
        int row = i >> 3, kq = (i & 7) * 4;
        aSrc[j] = Ab + (size_t)row * Kk + kq;
        aSt[j] = sb + row * (A_STRIDE_H * 2) + kq * 2;
        int krow = i >> 5, n = (i & 31) * 4;
        bSrc[j] = Bb + (size_t)krow * Nn + n;
        bSt[j] = sb + A_STAGE_B + krow * (B_STRIDE_H * 2) + n * 2;
    }

    float4 aR[8], bR[8];

    auto ldg_stage = [&](int kt) {
#pragma unroll
        for (int j = 0; j < 8; j++) aR[j] = *(const float4*)(aSrc[j] + (size_t)kt * BK);
#pragma unroll
        for (int j = 0; j < 8; j++) bR[j] = *(const float4*)(bSrc[j] + (size_t)kt * BK * Nn);
    };
    auto sts_stage = [&](int s) {
        const uint32_t soff = s * STAGE_B;
#pragma unroll
        for (int j = 0; j < 8; j++) {
            uint2 p = make_uint2(h2pack(aR[j].x, aR[j].y), h2pack(aR[j].z, aR[j].w));
            *(uint2*)(smem_raw + (aSt[j] - sb) + soff) = p;
        }
#pragma unroll
        for (int j = 0; j < 8; j++) {
            uint2 p = make_uint2(h2pack(bR[j].x, bR[j].y), h2pack(bR[j].z, bR[j].w));
            *(uint2*)(smem_raw + (bSt[j] - sb) + soff) = p;
        }
    };

    // ---- compute mapping: 4 warps, 2x2 of 64x64 warp tiles ----
    const int warp_m = wid >> 1;
    const int warp_n = wid & 1;
    const int m_base = warp_m * 64;
    const int nb     = warp_n * 64;
    const int g = lane >> 2;
    const int t = lane & 3;

    // ldmatrix lane-address components
    const int lrow8 = (lane & 7) + ((lane >> 3) & 1) * 8;  // row within 16
    const int lk8   = ((lane >> 4) & 1) * 8;               // k/n half select

    float acc[4][8][4];
#pragma unroll
    for (int i = 0; i < 4; i++)
#pragma unroll
        for (int j = 0; j < 8; j++)
#pragma unroll
            for (int r = 0; r < 4; r++) acc[i][j][r] = 0.0f;

    // prologue
    ldg_stage(0);
    sts_stage(0);
    __syncthreads();

#pragma unroll 1
    for (int kt = 0; kt < KT; kt++) {
        const int cur = kt & 1;

        if (kt + 1 < KT) ldg_stage(kt + 1);

        const uint32_t Abase = sb + cur * STAGE_B;
        const uint32_t Bbase = Abase + A_STAGE_B;

#pragma unroll
        for (int ks = 0; ks < 2; ks++) {     // 2 x k16 per BK=32
            const int k0 = ks * 16;

            uint32_t af[4][4];
#pragma unroll
            for (int i = 0; i < 4; i++) {
                uint32_t addr = Abase
                    + (m_base + i * 16 + lrow8) * (A_STRIDE_H * 2)
                    + (k0 + lk8) * 2;
                ldmatrix_x4(af[i][0], af[i][1], af[i][2], af[i][3], addr);
            }
            uint32_t bf[4][4];  // [n16 tile][r0=b0 lo, r1=b1 lo, r2=b0 hi, r3=b1 hi]
#pragma unroll
            for (int j2 = 0; j2 < 4; j2++) {
                uint32_t addr = Bbase
                    + (k0 + lrow8) * (B_STRIDE_H * 2)
                    + (nb + j2 * 16 + lk8) * 2;
                ldmatrix_x4_trans(bf[j2][0], bf[j2][1], bf[j2][2], bf[j2][3], addr);
            }
#pragma unroll
            for (int i = 0; i < 4; i++)
#pragma unroll
                for (int j = 0; j < 8; j++) {
                    const int j2 = j >> 1, h = (j & 1) * 2;
                    mma_f16(acc[i][j][0], acc[i][j][1], acc[i][j][2], acc[i][j][3],
                            af[i][0], af[i][1], af[i][2], af[i][3],
                            bf[j2][h + 0], bf[j2][h + 1]);
                }
        }

        if (kt + 1 < KT) sts_stage(cur ^ 1);
        __syncthreads();
    }

    // ---- epilogue (standard m16n8 C layout) ----
#pragma unroll
    for (int i = 0; i < 4; i++) {
        const int row0 = m_base + i * 16 + g;
#pragma unroll
        for (int j = 0; j < 8; j++) {
            const int col = nb + j * 8 + 2 * t;
            *(float2*)(Cb + (size_t)row0 * Nn + col) =
                make_float2(acc[i][j][0], acc[i][j][1]);
            *(float2*)(Cb + (size_t)(row0 + 8) * Nn + col) =
                make_float2(acc[i][j][2], acc[i][j][3]);
        }
    }
}

extern "C" void kernel_launch(void* const* d_in, const int* in_sizes, int n_in,
                              void* d_out, int out_size) {
    const float* x    = (const float*)d_in[0];  // [16, 256, 512]
    const float* path = (const float*)d_in[1];  // [16, 512, 2048]
    float* out = (float*)d_out;                 // [16, 256, 2048]

    dim3 grid(Nn / BN, Mm / BM, 16);  // (16, 2, 16) = 512 CTAs
    bmm_mma_f16_ldm<<<grid, THREADS>>>(x, path, out);
}